// round 13
// baseline (speedup 1.0000x reference)
#include <cuda_runtime.h>
#include <cuda_fp16.h>
#include <cstdint>
#include <cstddef>

#define Bb 16
#define Tt 128
#define Dd 256
#define HCOLS 128
#define NTHREADS 1024

// smem layout (bytes)
#define OFF_WA   0
#define SZ_WA    (8 * NTHREADS * 16)       // 131072: fp16 w+alpha interleaved uint4 rows
#define OFF_YB   (OFF_WA + SZ_WA)
#define YSLOT_B  1312                       // per slot: 2 halves x 656 (640 data + 16 pad)
#define SZ_YB    (4 * YSLOT_B)              // 5248
#define OFF_Y0H  (OFF_YB + SZ_YB)
#define SZ_Y0H   (4 * 640)                  // 2560
#define OFF_XT   (OFF_Y0H + SZ_Y0H)
#define SZ_XT    (2 * Tt * 4)               // 1024
#define OFF_RED  (OFF_XT + SZ_XT)
#define SZ_RED   (32 * 4)                   // redbuf[2 parities][16]
#define OFF_MB   (OFF_RED + SZ_RED)
#define SZ_MB    (4 * 8)                    // 4 slot barriers
#define SMEM_TOTAL (OFF_MB + SZ_MB)

__device__ __forceinline__ uint32_t my_cluster_rank() {
    uint32_t r; asm("mov.u32 %0, %%cluster_ctarank;" : "=r"(r)); return r;
}
__device__ __forceinline__ void cluster_sync_() {
    asm volatile("barrier.cluster.arrive.aligned;" ::: "memory");
    asm volatile("barrier.cluster.wait.aligned;" ::: "memory");
}
__device__ __forceinline__ uint32_t mapa_u32(uint32_t laddr, uint32_t rank) {
    uint32_t r;
    asm("mapa.shared::cluster.u32 %0, %1, %2;" : "=r"(r) : "r"(laddr), "r"(rank));
    return r;
}
__device__ __forceinline__ void mb_init(uint32_t addr, uint32_t count) {
    asm volatile("mbarrier.init.shared.b64 [%0], %1;" :: "r"(addr), "r"(count) : "memory");
}
__device__ __forceinline__ void mb_arrive_remote(uint32_t raddr) {
    asm volatile("mbarrier.arrive.release.cluster.shared::cluster.b64 _, [%0];"
                 :: "r"(raddr) : "memory");
}
__device__ __forceinline__ void mb_arrive_plain(uint32_t addr) {
    asm volatile("mbarrier.arrive.shared.b64 _, [%0];" :: "r"(addr) : "memory");
}
__device__ __forceinline__ void mb_expect_tx(uint32_t addr, uint32_t bytes) {
    asm volatile("mbarrier.arrive.expect_tx.shared.b64 _, [%0], %1;"
                 :: "r"(addr), "r"(bytes) : "memory");
}
// DSMEM bulk copy with tx completion on a (remote) mbarrier.
__device__ __forceinline__ void bulk_cluster(uint32_t dst, uint32_t src,
                                             uint32_t bytes, uint32_t mbar) {
    asm volatile(
        "cp.async.bulk.shared::cluster.shared::cta.mbarrier::complete_tx::bytes "
        "[%0], [%1], %2, [%3];"
        :: "r"(dst), "r"(src), "r"(bytes), "r"(mbar) : "memory");
}
__device__ __forceinline__ void fence_async() {
    asm volatile("fence.proxy.async.shared::cta;" ::: "memory");
}
__device__ __forceinline__ void mb_wait(uint32_t addr, uint32_t parity) {
    uint32_t done;
    asm volatile(
        "{\n\t.reg .pred p;\n\t"
        "mbarrier.try_wait.parity.acquire.cluster.shared::cta.b64 p, [%1], %2;\n\t"
        "selp.b32 %0, 1, 0, p;\n\t}"
        : "=r"(done) : "r"(addr), "r"(parity) : "memory");
    while (!done) {
        asm volatile(
            "{\n\t.reg .pred p;\n\t"
            "mbarrier.try_wait.parity.acquire.cluster.shared::cta.b64 p, [%1], %2, 0x989680;\n\t"
            "selp.b32 %0, 1, 0, p;\n\t}"
            : "=r"(done) : "r"(addr), "r"(parity) : "memory");
    }
}
__device__ __forceinline__ float tanh_ap(float x) {
    float y; asm("tanh.approx.f32 %0, %1;" : "=f"(y) : "f"(x)); return y;
}
__device__ __forceinline__ float grp8_sum(float v) {
    v += __shfl_xor_sync(0xffffffffu, v, 1);
    v += __shfl_xor_sync(0xffffffffu, v, 2);
    v += __shfl_xor_sync(0xffffffffu, v, 4);
    return v;
}
__device__ __forceinline__ void bar_named(int id, int n) {
    asm volatile("bar.sync %0, %1;" :: "r"(id), "r"(n) : "memory");
}

__global__ void __launch_bounds__(NTHREADS, 1) __cluster_dims__(4, 1, 1)
plastic_kernel(const int* __restrict__ x, const float* __restrict__ emb,
               const float* __restrict__ ws, const float* __restrict__ alphas,
               const float* __restrict__ etas, float* __restrict__ out)
{
    extern __shared__ __align__(16) char smem_raw[];
    uint4* wa      = reinterpret_cast<uint4*>(smem_raw + OFF_WA);   // [8][1024]
    char*  ybufc   = smem_raw + OFF_YB;    // [4 slots][2 halves][2 batches x 320 (+16 pad)]
    char*  y0hc    = smem_raw + OFF_Y0H;   // [4 slots][2 batches x 320]
    int*   xtok    = reinterpret_cast<int*>(smem_raw + OFF_XT);     // [2][128]
    float* redbuf  = reinterpret_cast<float*>(smem_raw + OFF_RED);  // [2][16]
    const uint32_t sbase = (uint32_t)__cvta_generic_to_shared(smem_raw);

    const int tid     = threadIdx.x;
    const int cluster = blockIdx.x >> 2;
    const int rank    = (int)my_cluster_rank();
    const int layer   = rank >> 1;
    const int half_   = rank & 1;
    const int col_off = half_ * HCOLS;
    const int partner = rank ^ 1;
    const int col     = tid >> 3;            // 0..127
    const int colg    = col_off + col;
    const int dgrp    = tid & 7;             // 0..7, d-range [dgrp*32, dgrp*32+32)
    const int wid     = tid >> 5, lane = tid & 31;

#define MB_ADDR(s)  (sbase + OFF_MB + (uint32_t)((s) * 8))

    // ---- init shared ----
    for (int i = tid; i < SZ_YB / 4; i += NTHREADS)
        reinterpret_cast<uint32_t*>(ybufc)[i] = 0u;
    for (int i = tid; i < SZ_Y0H / 4; i += NTHREADS)
        reinterpret_cast<uint32_t*>(y0hc)[i] = 0u;
    for (int i = tid; i < 2 * Tt; i += NTHREADS)
        xtok[i] = x[(cluster * 2 + (i >> 7)) * Tt + (i & 127)];
    if (tid == 0) {
        const uint32_t cnt = (layer == 1) ? 1u : 2u;
        for (int k = 0; k < 4; k++) mb_init(MB_ADDR(k), cnt);
        // startup expects (local, before cluster_sync is fine)
        if (layer == 1) {
            mb_expect_tx(MB_ADDR(0), 640);            // L0 y0(0) only
            for (int s = 1; s < 4; s++) mb_expect_tx(MB_ADDR(s), 1280);
        } else {
            mb_arrive_plain(MB_ADDR(0));              // t=0: no tx expected
            for (int s = 1; s < 4; s++) mb_expect_tx(MB_ADDR(s), 640);
        }
    }
    __syncthreads();

    const float eta = etas[layer];
    const __half2 om2 = __float2half2_rn(1.0f - eta);

    __half2 h2a[16], h2b[16];
#pragma unroll
    for (int i = 0; i < 16; i++) { h2a[i] = __float2half2_rn(0.f); h2b[i] = h2a[i]; }

    // ---- stage w + alpha (fp16): thread o = c*8 + (d>>5) owns (32 d, 1 col) ----
    {
        const float* wsrc = ws     + (size_t)layer * Dd * Dd;
        const float* asrc = alphas + (size_t)layer * Dd * Dd;
        for (int idx = tid; idx < Dd * HCOLS; idx += NTHREADS) {
            int d = idx >> 7, c = idx & 127;
            int o = c * 8 + (d >> 5);
            int j = (d & 31) >> 3;
            int k = d & 7;
            reinterpret_cast<__half*>(&wa[(2 * j) * NTHREADS + o])[k] =
                __float2half(wsrc[(size_t)d * Dd + col_off + c]);
            reinterpret_cast<__half*>(&wa[(2 * j + 1) * NTHREADS + o])[k] =
                __float2half(asrc[(size_t)d * Dd + col_off + c]);
        }
    }
    __syncthreads();

    const uint32_t del_partner = mapa_u32(sbase, (uint32_t)partner) - sbase;
    const uint32_t del_inter   = (layer == 0)
        ? (mapa_u32(sbase, (uint32_t)(rank + 2)) - sbase)
        : (mapa_u32(sbase, (uint32_t)(rank - 2)) - sbase);

    cluster_sync_();   // barriers armed + buffers zeroed everywhere

    // ---- startup credits: L1 -> its L0, slots 0..3 ----
    if (tid == 32 && layer == 1) {
#pragma unroll
        for (int s = 0; s < 4; s++)
            mb_arrive_remote(MB_ADDR(s) + del_inter);
    }

    float* const outB0 = out + (size_t)(cluster * 2 + 0) * Tt * Dd;
    float* const outB1 = out + (size_t)(cluster * 2 + 1) * Tt * Dd;
    const uint4* wthr = wa + tid;

    float embreg0 = 0.f, embreg1 = 0.f;
    if (layer == 0) {
        embreg0 = __ldg(&emb[(size_t)xtok[0] * Dd + colg]);
        embreg1 = __ldg(&emb[(size_t)xtok[Tt] * Dd + colg]);
    }

    for (int t = 0; t < Tt; ++t) {
        const int sc = t & 3, sp = (t + 3) & 3, n3 = (t + 1) & 3;
        const uint32_t par = (uint32_t)((t >> 2) & 1);

        mb_wait(MB_ADDR(sc), par);

        // re-arm this slot for step t+4 (or the L1 epilogue when t+4 == Tt)
        if (tid == 0) {
            if (layer == 1) {
                if (t + 4 < Tt)       mb_expect_tx(MB_ADDR(sc), 1280);
                else if (t + 4 == Tt) mb_expect_tx(MB_ADDR(sc), 640);
            } else if (t + 4 < Tt) {
                mb_expect_tx(MB_ADDR(sc), 640);
            }
        }

        // ---- fused dual-batch dot ----
        const char* ybB = ybufc + sp * YSLOT_B + (dgrp >> 2) * 656 + (dgrp & 3) * 80;
        __half2 accA0 = __float2half2_rn(0.f), accA1 = accA0;
        __half2 accB0 = accA0, accB1 = accA0;
#pragma unroll
        for (int j = 0; j < 4; j++) {
            uint4 wv = wthr[(2 * j) * NTHREADS];
            uint4 av = wthr[(2 * j + 1) * NTHREADS];
            uint4 y0v = *reinterpret_cast<const uint4*>(ybB + j * 16);
            uint4 y1v = *reinterpret_cast<const uint4*>(ybB + 320 + j * 16);
#define LANE(F)  F(x, 4 * j + 0, accA0, accB0)  F(y, 4 * j + 1, accA1, accB1) \
                 F(z, 4 * j + 2, accA0, accB0)  F(w, 4 * j + 3, accA1, accB1)
#define DOT2(c, hi, aA, aB)                                                        \
            {                                                                      \
                __half2 wl = *reinterpret_cast<__half2*>(&wv.c);                   \
                __half2 al = *reinterpret_cast<__half2*>(&av.c);                   \
                aA = __hfma2(*reinterpret_cast<__half2*>(&y0v.c),                  \
                             __hfma2(al, h2a[hi], wl), aA);                        \
                aB = __hfma2(*reinterpret_cast<__half2*>(&y1v.c),                  \
                             __hfma2(al, h2b[hi], wl), aB);                        \
            }
            LANE(DOT2)
#undef DOT2
#undef LANE
        }
        float2 fA = __half22float2(__hadd2(accA0, accA1));
        float2 fB = __half22float2(__hadd2(accB0, accB1));
        float acc0 = grp8_sum(fA.x + fA.y);
        float acc1 = grp8_sum(fB.x + fB.y);

        float inp0, inp1;
        if (layer == 0) { inp0 = embreg0; inp1 = embreg1; }
        else {
            const char* ib = y0hc + sc * 640 + (col >> 5) * 80;
            inp0 = __half2float(reinterpret_cast<const __half*>(ib)[col & 31]);
            inp1 = __half2float(reinterpret_cast<const __half*>(ib + 320)[col & 31]);
        }
        float y0 = tanh_ap(acc0 + inp0);
        float y1 = tanh_ap(acc1 + inp1);

        // ---- local y writes (one thread per column) ----
        if (dgrp == 0) {
            char* wb = ybufc + sc * YSLOT_B + half_ * 656 + (col >> 5) * 80;
            reinterpret_cast<__half*>(wb)[col & 31] = __float2half(y0);
            reinterpret_cast<__half*>(wb + 320)[col & 31] = __float2half(y1);
        }
        __syncthreads();   // slab complete before bulk reads it

        // ---- exchange: single bulk per channel, tx-completion on consumer ----
        const uint32_t slab = sbase + OFF_YB + (uint32_t)(sc * YSLOT_B + half_ * 656);
        if (tid == 0) {
            if (layer == 1 || t + 1 < Tt) {
                fence_async();
                bulk_cluster(slab + del_partner, slab, 640, MB_ADDR(n3) + del_partner);
            }
        }
        if (tid == 32) {
            if (layer == 0) {
                fence_async();
                bulk_cluster(sbase + OFF_Y0H + (uint32_t)(sc * 640) + del_inter,
                             slab, 640, MB_ADDR(sc) + del_inter);
            } else {
                mb_arrive_remote(MB_ADDR(sc) + del_inter);   // credit to my L0
            }
        }

        // ---- deferred: hebb (re-reads old y), emb prefetch ----
        {
            __half2 ey0 = __float2half2_rn(eta * y0);
            __half2 ey1 = __float2half2_rn(eta * y1);
#pragma unroll
            for (int j = 0; j < 4; j++) {
                uint4 y0v = *reinterpret_cast<const uint4*>(ybB + j * 16);
                uint4 y1v = *reinterpret_cast<const uint4*>(ybB + 320 + j * 16);
#define HEB(c, hi)                                                                 \
                h2a[hi] = __hfma2(h2a[hi], om2,                                    \
                    __hmul2(*reinterpret_cast<__half2*>(&y0v.c), ey0));            \
                h2b[hi] = __hfma2(h2b[hi], om2,                                    \
                    __hmul2(*reinterpret_cast<__half2*>(&y1v.c), ey1));
                HEB(x, 4 * j + 0) HEB(y, 4 * j + 1) HEB(z, 4 * j + 2) HEB(w, 4 * j + 3)
#undef HEB
            }
        }
        if (layer == 0 && t + 1 < Tt) {
            embreg0 = __ldg(&emb[(size_t)xtok[t + 1] * Dd + colg]);
            embreg1 = __ldg(&emb[(size_t)xtok[Tt + t + 1] * Dd + colg]);
        }

        // ---- softmax: warps 0..7 only, named barrier ----
        if (layer == 1 && t >= 1 && tid < 256) {
            float* rb = redbuf + (t & 1) * 16;
            const char* sb = ybufc + sp * YSLOT_B + (tid >> 7) * 656
                             + ((tid & 127) >> 5) * 80;
            float v0 = __half2float(reinterpret_cast<const __half*>(sb)[tid & 31]);
            float v1 = __half2float(reinterpret_cast<const __half*>(sb + 320)[tid & 31]);
            float ex0 = __expf(__fdividef(1.0f, 1.0f + __expf(-v0)));
            float ex1 = __expf(__fdividef(1.0f, 1.0f + __expf(-v1)));
            float w0 = ex0, w1 = ex1;
#pragma unroll
            for (int o = 16; o >= 1; o >>= 1) {
                w0 += __shfl_xor_sync(0xffffffffu, w0, o);
                w1 += __shfl_xor_sync(0xffffffffu, w1, o);
            }
            if (lane == 0) { rb[wid] = w0; rb[8 + wid] = w1; }
            bar_named(1, 256);
            float t0 = 0.f, t1 = 0.f;
#pragma unroll
            for (int k = 0; k < 8; k++) { t0 += rb[k]; t1 += rb[8 + k]; }
            if (tid >= col_off && tid < col_off + HCOLS) {
                outB0[(size_t)(t - 1) * Dd + tid] = __fdividef(ex0, t0);
                outB1[(size_t)(t - 1) * Dd + tid] = __fdividef(ex1, t1);
            }
        }
    }

    // ---- epilogue: L1 consumes partner's final slab on slot 0, phase 0 ----
    if (layer == 1) {
        mb_wait(MB_ADDR(0), 0u);
        if (tid < 256) {
            const int sp = 3;   // slot of y1(127)
            float* rb = redbuf;  // parity-0 half (last in-loop used parity 1)
            const char* sb = ybufc + sp * YSLOT_B + (tid >> 7) * 656
                             + ((tid & 127) >> 5) * 80;
            float v0 = __half2float(reinterpret_cast<const __half*>(sb)[tid & 31]);
            float v1 = __half2float(reinterpret_cast<const __half*>(sb + 320)[tid & 31]);
            float ex0 = __expf(__fdividef(1.0f, 1.0f + __expf(-v0)));
            float ex1 = __expf(__fdividef(1.0f, 1.0f + __expf(-v1)));
            float w0 = ex0, w1 = ex1;
#pragma unroll
            for (int o = 16; o >= 1; o >>= 1) {
                w0 += __shfl_xor_sync(0xffffffffu, w0, o);
                w1 += __shfl_xor_sync(0xffffffffu, w1, o);
            }
            if (lane == 0) { rb[wid] = w0; rb[8 + wid] = w1; }
            bar_named(1, 256);
            float t0 = 0.f, t1 = 0.f;
#pragma unroll
            for (int k = 0; k < 8; k++) { t0 += rb[k]; t1 += rb[8 + k]; }
            if (tid >= col_off && tid < col_off + HCOLS) {
                outB0[(size_t)(Tt - 1) * Dd + tid] = __fdividef(ex0, t0);
                outB1[(size_t)(Tt - 1) * Dd + tid] = __fdividef(ex1, t1);
            }
        }
    }

    cluster_sync_();   // keep smem alive until all peers are done
}

extern "C" void kernel_launch(void* const* d_in, const int* in_sizes, int n_in,
                              void* d_out, int out_size) {
    const int*   x      = (const int*)d_in[0];
    const float* emb    = (const float*)d_in[1];
    const float* ws     = (const float*)d_in[2];
    const float* alphas = (const float*)d_in[3];
    const float* etas   = (const float*)d_in[4];
    cudaFuncSetAttribute(plastic_kernel,
                         cudaFuncAttributeMaxDynamicSharedMemorySize, SMEM_TOTAL);
    plastic_kernel<<<(Bb / 2) * 4, NTHREADS, SMEM_TOTAL>>>(
        x, emb, ws, alphas, etas, (float*)d_out);
}